// round 1
// baseline (speedup 1.0000x reference)
#include <cuda_runtime.h>
#include <cuda_bf16.h>
#include <math.h>
#include <stdint.h>

// ---------------- problem constants ----------------
#define QLEN   1024
#define BSZ    2
#define DMODEL 1024
#define NHEAD  16
#define DHEAD  64
#define NLAYER 4
#define MLEN_  1024
#define KLEN_  2048
#define QKV3   (3*DMODEL)

// ---------------- scratch (device globals; no allocation) ----------------
__device__ float g_pos_emb[KLEN_*DMODEL];                     // 8 MB
__device__ float g_cat[KLEN_*BSZ*DMODEL];                     // 16 MB
__device__ float g_wheads[KLEN_*BSZ*QKV3];                    // 48 MB
__device__ float g_rhk[KLEN_*DMODEL];                         // 8 MB
__device__ float g_score[(size_t)BSZ*NHEAD*QLEN*KLEN_];       // 256 MB
__device__ float g_bd[(size_t)BSZ*NHEAD*QLEN*KLEN_];          // 256 MB
__device__ float g_attnvec[QLEN*BSZ*DMODEL];                  // 8 MB
__device__ float g_tmp[QLEN*BSZ*DMODEL];                      // 8 MB
__device__ float g_ff1[QLEN*BSZ*DMODEL];                      // 8 MB
__device__ float g_core[QLEN*BSZ*DMODEL];                     // 8 MB

// ---------------- positional embedding ----------------
__global__ void pos_emb_kernel() {
    int p = blockIdx.x;
    float pos = (float)(KLEN_ - 1 - p);
    for (int f = threadIdx.x; f < DMODEL/2; f += blockDim.x) {
        double e = -((double)(2*f) / (double)DMODEL) * log(10000.0);
        float invf = (float)exp(e);
        float arg = pos * invf;
        g_pos_emb[p*DMODEL + f]            = sinf(arg);
        g_pos_emb[p*DMODEL + DMODEL/2 + f] = cosf(arg);
    }
}

// ---------------- fp32 SGEMM: C = A(MxK) * B(KxN), row-major ----------------
template<bool RELU, bool HASBIAS>
__global__ void __launch_bounds__(256) sgemm_kernel(
    const float* __restrict__ A, const float* __restrict__ B,
    float* __restrict__ C, const float* __restrict__ bias,
    int M, int N, int K)
{
    __shared__ float As[8][128];
    __shared__ float Bs[8][128];
    int tid = threadIdx.x;
    int tm = tid >> 4, tn = tid & 15;
    int br = blockIdx.y, bc = blockIdx.x;
    const float* Ab = A + (size_t)br * 128 * K;
    const float* Bb = B + bc * 128;

    float acc[8][8];
    #pragma unroll
    for (int i = 0; i < 8; i++)
        #pragma unroll
        for (int j = 0; j < 8; j++) acc[i][j] = 0.f;

    int ar = tid >> 1;            // 0..127
    int ac = (tid & 1) * 4;       // 0 or 4
    int brow = tid >> 5;          // 0..7
    int bcol = (tid & 31) * 4;    // 0..124

    for (int k0 = 0; k0 < K; k0 += 8) {
        float4 av = *(const float4*)(Ab + (size_t)ar * K + k0 + ac);
        float4 bv = *(const float4*)(Bb + (size_t)(k0 + brow) * N + bcol);
        As[ac+0][ar] = av.x; As[ac+1][ar] = av.y;
        As[ac+2][ar] = av.z; As[ac+3][ar] = av.w;
        *(float4*)(&Bs[brow][bcol]) = bv;
        __syncthreads();
        #pragma unroll
        for (int c = 0; c < 8; c++) {
            float a[8], b[8];
            float4 a0 = *(const float4*)(&As[c][tm*8]);
            float4 a1 = *(const float4*)(&As[c][tm*8+4]);
            float4 b0 = *(const float4*)(&Bs[c][tn*8]);
            float4 b1 = *(const float4*)(&Bs[c][tn*8+4]);
            a[0]=a0.x;a[1]=a0.y;a[2]=a0.z;a[3]=a0.w;a[4]=a1.x;a[5]=a1.y;a[6]=a1.z;a[7]=a1.w;
            b[0]=b0.x;b[1]=b0.y;b[2]=b0.z;b[3]=b0.w;b[4]=b1.x;b[5]=b1.y;b[6]=b1.z;b[7]=b1.w;
            #pragma unroll
            for (int i = 0; i < 8; i++)
                #pragma unroll
                for (int j = 0; j < 8; j++)
                    acc[i][j] += a[i] * b[j];
        }
        __syncthreads();
    }

    #pragma unroll
    for (int i = 0; i < 8; i++) {
        int row = br*128 + tm*8 + i;
        float* Crow = C + (size_t)row * N + bc*128 + tn*8;
        #pragma unroll
        for (int j = 0; j < 8; j++) {
            float v = acc[i][j];
            if (HASBIAS) v += bias[bc*128 + tn*8 + j];
            if (RELU) v = fmaxf(v, 0.f);
            Crow[j] = v;
        }
    }
}

// ---------------- batched attention QK / Q·rhk GEMMs ----------------
// MODE 0: AC[z][i][j] = sum_d (q[i,b,n,d]+r_w_bias[n,d]) * k[j,b,n,d]
// MODE 1: BD[z][i][jr]= sum_d (q[i,b,n,d]+r_r_bias[n,d]) * rhk[jr,n,d]
template<int MODE>
__global__ void __launch_bounds__(256) attn_qk_kernel(const float* __restrict__ qbias)
{
    __shared__ float As[16][68];
    __shared__ float Bs[16][68];
    int tid = threadIdx.x;
    int j0 = blockIdx.x * 64;
    int i0 = blockIdx.y * 64;
    int z  = blockIdx.z;
    int bb = z >> 4, n = z & 15;
    int ty = tid >> 4, tx = tid & 15;

    float acc[4][4];
    #pragma unroll
    for (int i = 0; i < 4; i++)
        #pragma unroll
        for (int j = 0; j < 4; j++) acc[i][j] = 0.f;

    int lr = tid >> 2;          // 0..63
    int lc = (tid & 3) * 4;     // 0,4,8,12
    const float* qb = qbias + n * DHEAD;

    for (int d0 = 0; d0 < DHEAD; d0 += 16) {
        const float* qp = g_wheads + ((size_t)(MLEN_ + i0 + lr) * BSZ + bb) * QKV3
                          + n * DHEAD + d0 + lc;
        float4 av = *(const float4*)qp;
        float4 qb4 = *(const float4*)(qb + d0 + lc);
        av.x += qb4.x; av.y += qb4.y; av.z += qb4.z; av.w += qb4.w;
        float4 bv;
        if (MODE == 0) {
            bv = *(const float4*)(g_wheads + ((size_t)(j0 + lr) * BSZ + bb) * QKV3
                                  + DMODEL + n * DHEAD + d0 + lc);
        } else {
            bv = *(const float4*)(g_rhk + (size_t)(j0 + lr) * DMODEL + n * DHEAD + d0 + lc);
        }
        As[lc+0][lr]=av.x; As[lc+1][lr]=av.y; As[lc+2][lr]=av.z; As[lc+3][lr]=av.w;
        Bs[lc+0][lr]=bv.x; Bs[lc+1][lr]=bv.y; Bs[lc+2][lr]=bv.z; Bs[lc+3][lr]=bv.w;
        __syncthreads();
        #pragma unroll
        for (int c = 0; c < 16; c++) {
            float4 a4 = *(const float4*)(&As[c][ty*4]);
            float4 b4 = *(const float4*)(&Bs[c][tx*4]);
            float a[4] = {a4.x,a4.y,a4.z,a4.w};
            float b[4] = {b4.x,b4.y,b4.z,b4.w};
            #pragma unroll
            for (int i = 0; i < 4; i++)
                #pragma unroll
                for (int j = 0; j < 4; j++)
                    acc[i][j] += a[i] * b[j];
        }
        __syncthreads();
    }

    float* out = (MODE == 0) ? g_score : g_bd;
    #pragma unroll
    for (int i = 0; i < 4; i++) {
        int ii = i0 + ty*4 + i;
        float4 v = make_float4(acc[i][0], acc[i][1], acc[i][2], acc[i][3]);
        *(float4*)(out + ((size_t)z * QLEN + ii) * KLEN_ + j0 + tx*4) = v;
    }
}

// ---------------- fused score + rel-shift gather + mask + softmax ----------------
__global__ void __launch_bounds__(256) softmax_kernel()
{
    int i = blockIdx.x;
    int z = blockIdx.y;
    int tid = threadIdx.x;
    float* row = g_score + ((size_t)z * QLEN + i) * KLEN_;
    const float* bdrow = g_bd + ((size_t)z * QLEN + i) * KLEN_;
    const float scale = 0.125f;   // 1/sqrt(64)
    int limit = MLEN_ + i;

    float vals[8];
    float mx = -1e30f;
    #pragma unroll
    for (int u = 0; u < 8; u++) {
        int j = u * 256 + tid;
        float s;
        if (j <= limit) {
            int jr = j - i + (QLEN - 1);   // rel_shift gather; always in [0,KLEN)
            s = (row[j] + bdrow[jr]) * scale;
        } else {
            s = -1e30f;
        }
        vals[u] = s;
        mx = fmaxf(mx, s);
    }

    __shared__ float redm[8];
    __shared__ float reds[8];
    #pragma unroll
    for (int o = 16; o > 0; o >>= 1) mx = fmaxf(mx, __shfl_xor_sync(0xffffffffu, mx, o));
    if ((tid & 31) == 0) redm[tid >> 5] = mx;
    __syncthreads();
    mx = redm[0];
    #pragma unroll
    for (int w = 1; w < 8; w++) mx = fmaxf(mx, redm[w]);

    float sm = 0.f;
    #pragma unroll
    for (int u = 0; u < 8; u++) {
        float e = __expf(vals[u] - mx);
        vals[u] = e;
        sm += e;
    }
    #pragma unroll
    for (int o = 16; o > 0; o >>= 1) sm += __shfl_xor_sync(0xffffffffu, sm, o);
    if ((tid & 31) == 0) reds[tid >> 5] = sm;
    __syncthreads();
    float tot = reds[0];
    #pragma unroll
    for (int w = 1; w < 8; w++) tot += reds[w];
    float inv = 1.f / tot;

    #pragma unroll
    for (int u = 0; u < 8; u++) {
        int j = u * 256 + tid;
        row[j] = vals[u] * inv;
    }
}

// ---------------- attn_vec = prob @ v  (per b,n: 1024x2048 @ 2048x64) ----------------
__global__ void __launch_bounds__(256) attn_pv_kernel()
{
    __shared__ float Ps[16][68];
    __shared__ float Vs[16][68];
    int tid = threadIdx.x;
    int i0 = blockIdx.y * 64;
    int z  = blockIdx.z;
    int bb = z >> 4, n = z & 15;
    int ty = tid >> 4, tx = tid & 15;

    float acc[4][4];
    #pragma unroll
    for (int i = 0; i < 4; i++)
        #pragma unroll
        for (int j = 0; j < 4; j++) acc[i][j] = 0.f;

    const float* prob = g_score + (size_t)z * QLEN * KLEN_;
    int plr = tid >> 2;          // i-row 0..63
    int plc = (tid & 3) * 4;     // j within chunk
    int vlr = tid >> 4;          // j-row 0..15
    int vlc = (tid & 15) * 4;    // d

    for (int j0 = 0; j0 < KLEN_; j0 += 16) {
        float4 pv = *(const float4*)(prob + (size_t)(i0 + plr) * KLEN_ + j0 + plc);
        Ps[plc+0][plr]=pv.x; Ps[plc+1][plr]=pv.y; Ps[plc+2][plr]=pv.z; Ps[plc+3][plr]=pv.w;
        float4 vv = *(const float4*)(g_wheads + ((size_t)(j0 + vlr) * BSZ + bb) * QKV3
                                     + 2*DMODEL + n * DHEAD + vlc);
        *(float4*)(&Vs[vlr][vlc]) = vv;
        __syncthreads();
        #pragma unroll
        for (int c = 0; c < 16; c++) {
            float4 a4 = *(const float4*)(&Ps[c][ty*4]);
            float4 b4 = *(const float4*)(&Vs[c][tx*4]);
            float a[4] = {a4.x,a4.y,a4.z,a4.w};
            float b[4] = {b4.x,b4.y,b4.z,b4.w};
            #pragma unroll
            for (int i = 0; i < 4; i++)
                #pragma unroll
                for (int j = 0; j < 4; j++)
                    acc[i][j] += a[i] * b[j];
        }
        __syncthreads();
    }

    #pragma unroll
    for (int i = 0; i < 4; i++) {
        int row = i0 + ty*4 + i;
        float4 v = make_float4(acc[i][0], acc[i][1], acc[i][2], acc[i][3]);
        *(float4*)(g_attnvec + ((size_t)row * BSZ + bb) * DMODEL + n * DHEAD + tx*4) = v;
    }
}

// ---------------- residual add + layernorm (in-place on g_core) ----------------
__global__ void __launch_bounds__(256) add_ln_kernel(
    const float* __restrict__ x, const float* __restrict__ g, const float* __restrict__ b)
{
    int r = blockIdx.x;
    int tid = threadIdx.x;
    size_t base = (size_t)r * DMODEL + tid * 4;
    float4 c4 = *(const float4*)(g_core + base);
    float4 x4 = *(const float4*)(x + base);
    float v0 = c4.x + x4.x, v1 = c4.y + x4.y, v2 = c4.z + x4.z, v3 = c4.w + x4.w;

    __shared__ float red1[8];
    __shared__ float red2[8];

    float s = v0 + v1 + v2 + v3;
    #pragma unroll
    for (int o = 16; o > 0; o >>= 1) s += __shfl_xor_sync(0xffffffffu, s, o);
    if ((tid & 31) == 0) red1[tid >> 5] = s;
    __syncthreads();
    float tot = red1[0];
    #pragma unroll
    for (int w = 1; w < 8; w++) tot += red1[w];
    float mean = tot * (1.f / DMODEL);

    float d0 = v0 - mean, d1 = v1 - mean, d2 = v2 - mean, d3 = v3 - mean;
    float sq = d0*d0 + d1*d1 + d2*d2 + d3*d3;
    #pragma unroll
    for (int o = 16; o > 0; o >>= 1) sq += __shfl_xor_sync(0xffffffffu, sq, o);
    if ((tid & 31) == 0) red2[tid >> 5] = sq;
    __syncthreads();
    float tot2 = red2[0];
    #pragma unroll
    for (int w = 1; w < 8; w++) tot2 += red2[w];
    float var = tot2 * (1.f / DMODEL);
    float inv = rsqrtf(var + 1e-5f);

    float4 g4 = *(const float4*)(g + tid*4);
    float4 b4 = *(const float4*)(b + tid*4);
    float4 o4;
    o4.x = d0 * inv * g4.x + b4.x;
    o4.y = d1 * inv * g4.y + b4.y;
    o4.z = d2 * inv * g4.z + b4.z;
    o4.w = d3 * inv * g4.w + b4.w;
    *(float4*)(g_core + base) = o4;
}

// ---------------- launch ----------------
extern "C" void kernel_launch(void* const* d_in, const int* in_sizes, int n_in,
                              void* d_out, int out_size)
{
    const float* mems = (const float*)d_in[0];
    const float* raw  = (const float*)d_in[1];
    // d_in[2] = attention_mask (recomputed in-kernel; ignored)
    const float* rwb  = (const float*)d_in[3];
    const float* rrb  = (const float*)d_in[4];
    const float* qkvw = (const float*)d_in[5];
    const float* rw   = (const float*)d_in[6];
    const float* ow   = (const float*)d_in[7];
    const float* ln1g = (const float*)d_in[8];
    const float* ln1b = (const float*)d_in[9];
    const float* ffw1 = (const float*)d_in[10];
    const float* ffb1 = (const float*)d_in[11];
    const float* ffw2 = (const float*)d_in[12];
    const float* ffb2 = (const float*)d_in[13];
    const float* ln2g = (const float*)d_in[14];
    const float* ln2b = (const float*)d_in[15];

    float *p_pos, *p_cat, *p_wheads, *p_rhk, *p_attnvec, *p_tmp, *p_ff1, *p_core;
    cudaGetSymbolAddress((void**)&p_pos, g_pos_emb);
    cudaGetSymbolAddress((void**)&p_cat, g_cat);
    cudaGetSymbolAddress((void**)&p_wheads, g_wheads);
    cudaGetSymbolAddress((void**)&p_rhk, g_rhk);
    cudaGetSymbolAddress((void**)&p_attnvec, g_attnvec);
    cudaGetSymbolAddress((void**)&p_tmp, g_tmp);
    cudaGetSymbolAddress((void**)&p_ff1, g_ff1);
    cudaGetSymbolAddress((void**)&p_core, g_core);

    const size_t CORE_N = (size_t)QLEN * BSZ * DMODEL;         // 2097152
    const size_t MEMS_N = (size_t)(NLAYER + 1) * CORE_N;       // 10485760
    const size_t CORE_BYTES = CORE_N * sizeof(float);

    float* out_core = nullptr;
    float* out_mems = nullptr;
    if ((size_t)out_size == CORE_N + MEMS_N) {
        out_core = (float*)d_out;
        out_mems = (float*)d_out + CORE_N;
    } else if ((size_t)out_size == MEMS_N) {
        out_mems = (float*)d_out;
    } else {
        out_core = (float*)d_out;
    }

    pos_emb_kernel<<<KLEN_, 256>>>();
    cudaMemcpyAsync(p_core, raw, CORE_BYTES, cudaMemcpyDeviceToDevice);
    if (out_mems)
        cudaMemcpyAsync(out_mems, raw, CORE_BYTES, cudaMemcpyDeviceToDevice);

    for (int l = 0; l < NLAYER; l++) {
        // cat = [mems[l]; core]
        cudaMemcpyAsync(p_cat, mems + (size_t)l * CORE_N, CORE_BYTES, cudaMemcpyDeviceToDevice);
        cudaMemcpyAsync(p_cat + CORE_N, p_core, CORE_BYTES, cudaMemcpyDeviceToDevice);

        // w_heads = cat @ qkv_w[l]    (4096 x 3072 x 1024)
        sgemm_kernel<false,false><<<dim3(QKV3/128, (KLEN_*BSZ)/128), 256>>>(
            p_cat, qkvw + (size_t)l * DMODEL * QKV3, p_wheads, nullptr,
            KLEN_*BSZ, QKV3, DMODEL);

        // r_head_k = pos_emb @ r_w[l]  (2048 x 1024 x 1024)
        sgemm_kernel<false,false><<<dim3(DMODEL/128, KLEN_/128), 256>>>(
            p_pos, rw + (size_t)l * DMODEL * DMODEL, p_rhk, nullptr,
            KLEN_, DMODEL, DMODEL);

        // AC and BD batched GEMMs
        attn_qk_kernel<0><<<dim3(KLEN_/64, QLEN/64, BSZ*NHEAD), 256>>>(rwb);
        attn_qk_kernel<1><<<dim3(KLEN_/64, QLEN/64, BSZ*NHEAD), 256>>>(rrb);

        // score = (AC + shift(BD)) * scale, mask, softmax
        softmax_kernel<<<dim3(QLEN, BSZ*NHEAD), 256>>>();

        // attn_vec = prob @ v
        attn_pv_kernel<<<dim3(1, QLEN/64, BSZ*NHEAD), 256>>>();

        // attn_out = attn_vec @ o_w[l]
        sgemm_kernel<false,false><<<dim3(DMODEL/128, (QLEN*BSZ)/128), 256>>>(
            p_attnvec, ow + (size_t)l * DMODEL * DMODEL, p_tmp, nullptr,
            QLEN*BSZ, DMODEL, DMODEL);

        // core = LN(core + attn_out)
        add_ln_kernel<<<QLEN*BSZ, 256>>>(p_tmp, ln1g + l*DMODEL, ln1b + l*DMODEL);

        // ff1 = relu(core @ ff_w1 + b1)
        sgemm_kernel<true,true><<<dim3(DMODEL/128, (QLEN*BSZ)/128), 256>>>(
            p_core, ffw1 + (size_t)l * DMODEL * DMODEL, p_ff1, ffb1 + l*DMODEL,
            QLEN*BSZ, DMODEL, DMODEL);

        // ff2 = ff1 @ ff_w2 + b2
        sgemm_kernel<false,true><<<dim3(DMODEL/128, (QLEN*BSZ)/128), 256>>>(
            p_ff1, ffw2 + (size_t)l * DMODEL * DMODEL, p_tmp, ffb2 + l*DMODEL,
            QLEN*BSZ, DMODEL, DMODEL);

        // core = LN(core + ff)
        add_ln_kernel<<<QLEN*BSZ, 256>>>(p_tmp, ln2g + l*DMODEL, ln2b + l*DMODEL);

        if (out_mems)
            cudaMemcpyAsync(out_mems + (size_t)(l+1) * CORE_N, p_core, CORE_BYTES,
                            cudaMemcpyDeviceToDevice);
    }

    if (out_core)
        cudaMemcpyAsync(out_core, p_core, CORE_BYTES, cudaMemcpyDeviceToDevice);
}

// round 2
// speedup vs baseline: 2.7387x; 2.7387x over previous
#include <cuda_runtime.h>
#include <cuda_bf16.h>
#include <math.h>
#include <stdint.h>

// ---------------- problem constants ----------------
#define QLEN   1024
#define BSZ    2
#define DMODEL 1024
#define NHEAD  16
#define DHEAD  64
#define NLAYER 4
#define MLEN_  1024
#define KLEN_  2048
#define QKV3   (3*DMODEL)

// ---------------- scratch (device globals; no allocation) ----------------
__device__ float g_pos_emb[KLEN_*DMODEL];                     // 8 MB
__device__ float g_cat[KLEN_*BSZ*DMODEL];                     // 16 MB
__device__ float g_wheads[KLEN_*BSZ*QKV3];                    // 48 MB
__device__ float g_rhk[KLEN_*DMODEL];                         // 8 MB
__device__ float g_score[(size_t)BSZ*NHEAD*QLEN*KLEN_];       // 256 MB
__device__ float g_bd[(size_t)BSZ*NHEAD*QLEN*KLEN_];          // 256 MB
__device__ float g_attnvec[QLEN*BSZ*DMODEL];                  // 8 MB
__device__ float g_tmp[QLEN*BSZ*DMODEL];                      // 8 MB
__device__ float g_ff1[QLEN*BSZ*DMODEL];                      // 8 MB
__device__ float g_core[QLEN*BSZ*DMODEL];                     // 8 MB

// ---------------- helpers ----------------
__device__ __forceinline__ uint32_t f2tf(float f) {
    uint32_t r;
    asm("cvt.rna.tf32.f32 %0, %1;" : "=r"(r) : "f"(f));
    return r;
}

__device__ __forceinline__ void mma_tf32(float* c,
    uint32_t a0, uint32_t a1, uint32_t a2, uint32_t a3,
    uint32_t b0, uint32_t b1)
{
    asm volatile(
        "mma.sync.aligned.m16n8k8.row.col.f32.tf32.tf32.f32 "
        "{%0,%1,%2,%3}, {%4,%5,%6,%7}, {%8,%9}, {%0,%1,%2,%3};\n"
        : "+f"(c[0]), "+f"(c[1]), "+f"(c[2]), "+f"(c[3])
        : "r"(a0), "r"(a1), "r"(a2), "r"(a3), "r"(b0), "r"(b1));
}

// ---------------- positional embedding ----------------
__global__ void pos_emb_kernel() {
    int p = blockIdx.x;
    float pos = (float)(KLEN_ - 1 - p);
    for (int f = threadIdx.x; f < DMODEL/2; f += blockDim.x) {
        double e = -((double)(2*f) / (double)DMODEL) * log(10000.0);
        float invf = (float)exp(e);
        float arg = pos * invf;
        g_pos_emb[p*DMODEL + f]            = sinf(arg);
        g_pos_emb[p*DMODEL + DMODEL/2 + f] = cosf(arg);
    }
}

// ---------------- TF32 tensor-core dense GEMM ----------------
// C = A(MxK) * B(KxN) [+ bias][relu], row-major, M%128==0, N%128==0, K%16==0
template<bool RELU, bool HASBIAS>
__global__ void __launch_bounds__(256) gemm_tc(
    const float* __restrict__ A, const float* __restrict__ B,
    float* __restrict__ C, const float* __restrict__ bias,
    int M, int N, int K)
{
    // A stored [m][k] stride 20 (20%32==4 -> conflict-free frag loads)
    // B stored [k][n] stride 136 (136%32==8 -> conflict-free frag loads)
    __shared__ uint32_t As[2][128][20];
    __shared__ uint32_t Bs[2][16][136];

    const int tid  = threadIdx.x;
    const int lane = tid & 31;
    const int wid  = tid >> 5;
    const int wm   = (wid >> 2) * 64;   // warp row offset
    const int wn   = (wid & 3) * 32;    // warp col offset
    const int br   = blockIdx.y, bc = blockIdx.x;
    const int lg   = lane >> 2;         // 0..7
    const int lk   = lane & 3;          // 0..3

    float acc[4][4][4];
    #pragma unroll
    for (int i = 0; i < 4; i++)
        #pragma unroll
        for (int j = 0; j < 4; j++)
            #pragma unroll
            for (int r = 0; r < 4; r++) acc[i][j][r] = 0.f;

    const int ar = tid >> 2;            // 0..63 (rows ar, ar+64)
    const int ac = (tid & 3) * 4;       // 0,4,8,12
    const int bk = tid >> 5;            // 0..7 (rows bk, bk+8)
    const int bn = (tid & 31) * 4;      // 0..124

    const float* Ap = A + (size_t)(br*128 + ar) * K + ac;
    const float* Bp = B + (size_t)bk * N + bc*128 + bn;

    float4 pa0, pa1, pb0, pb1;
    pa0 = *(const float4*)(Ap);
    pa1 = *(const float4*)(Ap + (size_t)64 * K);
    pb0 = *(const float4*)(Bp);
    pb1 = *(const float4*)(Bp + (size_t)8 * N);

    const int nIter = K >> 4;

    // store tile 0 into buffer 0
    *(uint4*)&As[0][ar][ac]    = make_uint4(f2tf(pa0.x), f2tf(pa0.y), f2tf(pa0.z), f2tf(pa0.w));
    *(uint4*)&As[0][ar+64][ac] = make_uint4(f2tf(pa1.x), f2tf(pa1.y), f2tf(pa1.z), f2tf(pa1.w));
    *(uint4*)&Bs[0][bk][bn]    = make_uint4(f2tf(pb0.x), f2tf(pb0.y), f2tf(pb0.z), f2tf(pb0.w));
    *(uint4*)&Bs[0][bk+8][bn]  = make_uint4(f2tf(pb1.x), f2tf(pb1.y), f2tf(pb1.z), f2tf(pb1.w));
    __syncthreads();

    for (int it = 0; it < nIter; ++it) {
        const int cur = it & 1;
        if (it + 1 < nIter) {
            const float* Ap2 = Ap + (it+1)*16;
            const float* Bp2 = Bp + (size_t)(it+1)*16 * N;
            pa0 = *(const float4*)(Ap2);
            pa1 = *(const float4*)(Ap2 + (size_t)64 * K);
            pb0 = *(const float4*)(Bp2);
            pb1 = *(const float4*)(Bp2 + (size_t)8 * N);
        }

        #pragma unroll
        for (int s = 0; s < 2; s++) {
            const int k0 = s*8 + lk;
            uint32_t bf[4][2];
            #pragma unroll
            for (int nt = 0; nt < 4; nt++) {
                int n = wn + nt*8 + lg;
                bf[nt][0] = Bs[cur][k0][n];
                bf[nt][1] = Bs[cur][k0+4][n];
            }
            #pragma unroll
            for (int mt = 0; mt < 4; mt++) {
                int m = wm + mt*16 + lg;
                uint32_t a0 = As[cur][m][k0];
                uint32_t a1 = As[cur][m+8][k0];
                uint32_t a2 = As[cur][m][k0+4];
                uint32_t a3 = As[cur][m+8][k0+4];
                #pragma unroll
                for (int nt = 0; nt < 4; nt++)
                    mma_tf32(acc[mt][nt], a0, a1, a2, a3, bf[nt][0], bf[nt][1]);
            }
        }

        if (it + 1 < nIter) {
            const int nxt = (it+1) & 1;
            *(uint4*)&As[nxt][ar][ac]    = make_uint4(f2tf(pa0.x), f2tf(pa0.y), f2tf(pa0.z), f2tf(pa0.w));
            *(uint4*)&As[nxt][ar+64][ac] = make_uint4(f2tf(pa1.x), f2tf(pa1.y), f2tf(pa1.z), f2tf(pa1.w));
            *(uint4*)&Bs[nxt][bk][bn]    = make_uint4(f2tf(pb0.x), f2tf(pb0.y), f2tf(pb0.z), f2tf(pb0.w));
            *(uint4*)&Bs[nxt][bk+8][bn]  = make_uint4(f2tf(pb1.x), f2tf(pb1.y), f2tf(pb1.z), f2tf(pb1.w));
            __syncthreads();
        }
    }

    // epilogue
    #pragma unroll
    for (int mt = 0; mt < 4; mt++) {
        int r0 = br*128 + wm + mt*16 + lg;
        #pragma unroll
        for (int nt = 0; nt < 4; nt++) {
            int c0 = bc*128 + wn + nt*8 + lk*2;
            float v0 = acc[mt][nt][0], v1 = acc[mt][nt][1];
            float v2 = acc[mt][nt][2], v3 = acc[mt][nt][3];
            if (HASBIAS) {
                float b0v = bias[c0], b1v = bias[c0+1];
                v0 += b0v; v1 += b1v; v2 += b0v; v3 += b1v;
            }
            if (RELU) {
                v0 = fmaxf(v0, 0.f); v1 = fmaxf(v1, 0.f);
                v2 = fmaxf(v2, 0.f); v3 = fmaxf(v3, 0.f);
            }
            *(float2*)(C + (size_t)r0 * N + c0)     = make_float2(v0, v1);
            *(float2*)(C + (size_t)(r0+8) * N + c0) = make_float2(v2, v3);
        }
    }
}

// ---------------- batched AC / BD GEMMs (tensor core, K=64) ----------------
// MODE 0: AC[z][i][j]  = sum_d (q[i,b,n,d]+r_w_bias[n,d]) * k[j,b,n,d]
// MODE 1: BD[z][i][jr] = sum_d (q[i,b,n,d]+r_r_bias[n,d]) * rhk[jr,n,d]
template<int MODE>
__global__ void __launch_bounds__(256) attn_qk_tc(const float* __restrict__ qbias)
{
    const int j0 = blockIdx.x * 128;
    const int i0 = blockIdx.y * 64;
    // causal-mask / rel-shift block skip
    if (MODE == 0) { if (j0 > MLEN_ + i0 + 63) return; }
    else           { if (j0 + 127 < (QLEN - 1) - (i0 + 63)) return; }

    __shared__ uint32_t As[64][68];    // [i][d], 68%32==4
    __shared__ uint32_t Bs[128][68];   // [j][d]

    const int tid  = threadIdx.x;
    const int lane = tid & 31;
    const int wid  = tid >> 5;
    const int z    = blockIdx.z;
    const int bb   = z >> 4, n = z & 15;
    const int lg   = lane >> 2, lk = lane & 3;

    const float* qb = qbias + n * DHEAD;
    #pragma unroll
    for (int p = 0; p < 4; p++) {
        int f = tid + 256*p;
        int r = f >> 4, c4 = (f & 15) * 4;
        const float* qp = g_wheads + ((size_t)(MLEN_ + i0 + r) * BSZ + bb) * QKV3
                          + n * DHEAD + c4;
        float4 v = *(const float4*)qp;
        float4 bv = *(const float4*)(qb + c4);
        *(uint4*)&As[r][c4] = make_uint4(f2tf(v.x+bv.x), f2tf(v.y+bv.y),
                                         f2tf(v.z+bv.z), f2tf(v.w+bv.w));
    }
    #pragma unroll
    for (int p = 0; p < 8; p++) {
        int f = tid + 256*p;
        int r = f >> 4, c4 = (f & 15) * 4;
        const float* kp = (MODE == 0)
            ? g_wheads + ((size_t)(j0 + r) * BSZ + bb) * QKV3 + DMODEL + n * DHEAD + c4
            : g_rhk + (size_t)(j0 + r) * DMODEL + n * DHEAD + c4;
        float4 v = *(const float4*)kp;
        *(uint4*)&Bs[r][c4] = make_uint4(f2tf(v.x), f2tf(v.y), f2tf(v.z), f2tf(v.w));
    }
    __syncthreads();

    const int wm = (wid >> 2) * 32;   // 2 warp rows
    const int wn = (wid & 3) * 32;    // 4 warp cols
    float acc[2][4][4];
    #pragma unroll
    for (int i = 0; i < 2; i++)
        #pragma unroll
        for (int j = 0; j < 4; j++)
            #pragma unroll
            for (int r = 0; r < 4; r++) acc[i][j][r] = 0.f;

    #pragma unroll
    for (int s = 0; s < 8; s++) {
        const int k0 = s*8 + lk;
        uint32_t bf[4][2];
        #pragma unroll
        for (int nt = 0; nt < 4; nt++) {
            int j = wn + nt*8 + lg;
            bf[nt][0] = Bs[j][k0];
            bf[nt][1] = Bs[j][k0+4];
        }
        #pragma unroll
        for (int mt = 0; mt < 2; mt++) {
            int m = wm + mt*16 + lg;
            uint32_t a0 = As[m][k0];
            uint32_t a1 = As[m+8][k0];
            uint32_t a2 = As[m][k0+4];
            uint32_t a3 = As[m+8][k0+4];
            #pragma unroll
            for (int nt = 0; nt < 4; nt++)
                mma_tf32(acc[mt][nt], a0, a1, a2, a3, bf[nt][0], bf[nt][1]);
        }
    }

    float* out = (MODE == 0) ? g_score : g_bd;
    #pragma unroll
    for (int mt = 0; mt < 2; mt++) {
        int r0 = i0 + wm + mt*16 + lg;
        #pragma unroll
        for (int nt = 0; nt < 4; nt++) {
            int c0 = j0 + wn + nt*8 + lk*2;
            *(float2*)(out + ((size_t)z * QLEN + r0) * KLEN_ + c0)
                = make_float2(acc[mt][nt][0], acc[mt][nt][1]);
            *(float2*)(out + ((size_t)z * QLEN + r0 + 8) * KLEN_ + c0)
                = make_float2(acc[mt][nt][2], acc[mt][nt][3]);
        }
    }
}

// ---------------- fused score + rel-shift gather + mask + softmax ----------------
__global__ void __launch_bounds__(256) softmax_kernel()
{
    int i = blockIdx.x;
    int z = blockIdx.y;
    int tid = threadIdx.x;
    float* row = g_score + ((size_t)z * QLEN + i) * KLEN_;
    const float* bdrow = g_bd + ((size_t)z * QLEN + i) * KLEN_;
    const float scale = 0.125f;
    int limit = MLEN_ + i;

    float vals[8];
    float mx = -1e30f;
    #pragma unroll
    for (int u = 0; u < 8; u++) {
        int j = u * 256 + tid;
        float s;
        if (j <= limit) {
            int jr = j - i + (QLEN - 1);
            s = (row[j] + bdrow[jr]) * scale;
        } else {
            s = -1e30f;
        }
        vals[u] = s;
        mx = fmaxf(mx, s);
    }

    __shared__ float redm[8];
    __shared__ float reds[8];
    #pragma unroll
    for (int o = 16; o > 0; o >>= 1) mx = fmaxf(mx, __shfl_xor_sync(0xffffffffu, mx, o));
    if ((tid & 31) == 0) redm[tid >> 5] = mx;
    __syncthreads();
    mx = redm[0];
    #pragma unroll
    for (int w = 1; w < 8; w++) mx = fmaxf(mx, redm[w]);

    float sm = 0.f;
    #pragma unroll
    for (int u = 0; u < 8; u++) {
        float e = __expf(vals[u] - mx);
        vals[u] = e;
        sm += e;
    }
    #pragma unroll
    for (int o = 16; o > 0; o >>= 1) sm += __shfl_xor_sync(0xffffffffu, sm, o);
    if ((tid & 31) == 0) reds[tid >> 5] = sm;
    __syncthreads();
    float tot = reds[0];
    #pragma unroll
    for (int w = 1; w < 8; w++) tot += reds[w];
    float inv = 1.f / tot;

    #pragma unroll
    for (int u = 0; u < 8; u++) {
        int j = u * 256 + tid;
        row[j] = vals[u] * inv;
    }
}

// ---------------- attn_vec = prob @ v (tensor core) ----------------
__global__ void __launch_bounds__(256) attn_pv_tc()
{
    __shared__ uint32_t Ps[64][36];   // [i][j], 36%32==4
    __shared__ uint32_t Vs[32][72];   // [j][d], 72%32==8

    const int tid  = threadIdx.x;
    const int lane = tid & 31;
    const int wid  = tid >> 5;
    const int i0   = blockIdx.y * 64;
    const int z    = blockIdx.x;
    const int bb   = z >> 4, n = z & 15;
    const int lg   = lane >> 2, lk = lane & 3;
    const int wm   = (wid >> 2) * 32;
    const int wn   = (wid & 3) * 16;

    float acc[2][2][4];
    #pragma unroll
    for (int i = 0; i < 2; i++)
        #pragma unroll
        for (int j = 0; j < 2; j++)
            #pragma unroll
            for (int r = 0; r < 4; r++) acc[i][j][r] = 0.f;

    const float* prob = g_score + (size_t)z * QLEN * KLEN_;
    const int jmax = MLEN_ + i0 + 64;      // cols beyond are exactly zero prob
    const int nIter = (jmax + 31) / 32;

    for (int it = 0; it < nIter; it++) {
        const int j0 = it * 32;
        #pragma unroll
        for (int p = 0; p < 2; p++) {
            int f = tid + 256*p;
            int r = f >> 3, c4 = (f & 7) * 4;
            float4 v = *(const float4*)(prob + (size_t)(i0 + r) * KLEN_ + j0 + c4);
            *(uint4*)&Ps[r][c4] = make_uint4(f2tf(v.x), f2tf(v.y), f2tf(v.z), f2tf(v.w));
        }
        #pragma unroll
        for (int p = 0; p < 2; p++) {
            int f = tid + 256*p;
            int r = f >> 4, c4 = (f & 15) * 4;
            float4 v = *(const float4*)(g_wheads + ((size_t)(j0 + r) * BSZ + bb) * QKV3
                                        + 2*DMODEL + n * DHEAD + c4);
            *(uint4*)&Vs[r][c4] = make_uint4(f2tf(v.x), f2tf(v.y), f2tf(v.z), f2tf(v.w));
        }
        __syncthreads();

        #pragma unroll
        for (int s = 0; s < 4; s++) {
            const int k0 = s*8 + lk;
            uint32_t bf[2][2];
            #pragma unroll
            for (int nt = 0; nt < 2; nt++) {
                int d = wn + nt*8 + lg;
                bf[nt][0] = Vs[k0][d];
                bf[nt][1] = Vs[k0+4][d];
            }
            #pragma unroll
            for (int mt = 0; mt < 2; mt++) {
                int m = wm + mt*16 + lg;
                uint32_t a0 = Ps[m][k0];
                uint32_t a1 = Ps[m+8][k0];
                uint32_t a2 = Ps[m][k0+4];
                uint32_t a3 = Ps[m+8][k0+4];
                #pragma unroll
                for (int nt = 0; nt < 2; nt++)
                    mma_tf32(acc[mt][nt], a0, a1, a2, a3, bf[nt][0], bf[nt][1]);
            }
        }
        __syncthreads();
    }

    #pragma unroll
    for (int mt = 0; mt < 2; mt++) {
        int r0 = i0 + wm + mt*16 + lg;
        #pragma unroll
        for (int nt = 0; nt < 2; nt++) {
            int c0 = wn + nt*8 + lk*2;
            *(float2*)(g_attnvec + ((size_t)r0 * BSZ + bb) * DMODEL + n * DHEAD + c0)
                = make_float2(acc[mt][nt][0], acc[mt][nt][1]);
            *(float2*)(g_attnvec + ((size_t)(r0+8) * BSZ + bb) * DMODEL + n * DHEAD + c0)
                = make_float2(acc[mt][nt][2], acc[mt][nt][3]);
        }
    }
}

// ---------------- residual add + layernorm (in-place on g_core) ----------------
__global__ void __launch_bounds__(256) add_ln_kernel(
    const float* __restrict__ x, const float* __restrict__ g, const float* __restrict__ b)
{
    int r = blockIdx.x;
    int tid = threadIdx.x;
    size_t base = (size_t)r * DMODEL + tid * 4;
    float4 c4 = *(const float4*)(g_core + base);
    float4 x4 = *(const float4*)(x + base);
    float v0 = c4.x + x4.x, v1 = c4.y + x4.y, v2 = c4.z + x4.z, v3 = c4.w + x4.w;

    __shared__ float red1[8];
    __shared__ float red2[8];

    float s = v0 + v1 + v2 + v3;
    #pragma unroll
    for (int o = 16; o > 0; o >>= 1) s += __shfl_xor_sync(0xffffffffu, s, o);
    if ((tid & 31) == 0) red1[tid >> 5] = s;
    __syncthreads();
    float tot = red1[0];
    #pragma unroll
    for (int w = 1; w < 8; w++) tot += red1[w];
    float mean = tot * (1.f / DMODEL);

    float d0 = v0 - mean, d1 = v1 - mean, d2 = v2 - mean, d3 = v3 - mean;
    float sq = d0*d0 + d1*d1 + d2*d2 + d3*d3;
    #pragma unroll
    for (int o = 16; o > 0; o >>= 1) sq += __shfl_xor_sync(0xffffffffu, sq, o);
    if ((tid & 31) == 0) red2[tid >> 5] = sq;
    __syncthreads();
    float tot2 = red2[0];
    #pragma unroll
    for (int w = 1; w < 8; w++) tot2 += red2[w];
    float var = tot2 * (1.f / DMODEL);
    float inv = rsqrtf(var + 1e-5f);

    float4 g4 = *(const float4*)(g + tid*4);
    float4 b4 = *(const float4*)(b + tid*4);
    float4 o4;
    o4.x = d0 * inv * g4.x + b4.x;
    o4.y = d1 * inv * g4.y + b4.y;
    o4.z = d2 * inv * g4.z + b4.z;
    o4.w = d3 * inv * g4.w + b4.w;
    *(float4*)(g_core + base) = o4;
}

// ---------------- launch ----------------
extern "C" void kernel_launch(void* const* d_in, const int* in_sizes, int n_in,
                              void* d_out, int out_size)
{
    const float* mems = (const float*)d_in[0];
    const float* raw  = (const float*)d_in[1];
    const float* rwb  = (const float*)d_in[3];
    const float* rrb  = (const float*)d_in[4];
    const float* qkvw = (const float*)d_in[5];
    const float* rw   = (const float*)d_in[6];
    const float* ow   = (const float*)d_in[7];
    const float* ln1g = (const float*)d_in[8];
    const float* ln1b = (const float*)d_in[9];
    const float* ffw1 = (const float*)d_in[10];
    const float* ffb1 = (const float*)d_in[11];
    const float* ffw2 = (const float*)d_in[12];
    const float* ffb2 = (const float*)d_in[13];
    const float* ln2g = (const float*)d_in[14];
    const float* ln2b = (const float*)d_in[15];

    float *p_pos, *p_cat, *p_wheads, *p_rhk, *p_attnvec, *p_tmp, *p_ff1, *p_core;
    cudaGetSymbolAddress((void**)&p_pos, g_pos_emb);
    cudaGetSymbolAddress((void**)&p_cat, g_cat);
    cudaGetSymbolAddress((void**)&p_wheads, g_wheads);
    cudaGetSymbolAddress((void**)&p_rhk, g_rhk);
    cudaGetSymbolAddress((void**)&p_attnvec, g_attnvec);
    cudaGetSymbolAddress((void**)&p_tmp, g_tmp);
    cudaGetSymbolAddress((void**)&p_ff1, g_ff1);
    cudaGetSymbolAddress((void**)&p_core, g_core);

    const size_t CORE_N = (size_t)QLEN * BSZ * DMODEL;
    const size_t MEMS_N = (size_t)(NLAYER + 1) * CORE_N;
    const size_t CORE_BYTES = CORE_N * sizeof(float);

    float* out_core = nullptr;
    float* out_mems = nullptr;
    if ((size_t)out_size == CORE_N + MEMS_N) {
        out_core = (float*)d_out;
        out_mems = (float*)d_out + CORE_N;
    } else if ((size_t)out_size == MEMS_N) {
        out_mems = (float*)d_out;
    } else {
        out_core = (float*)d_out;
    }

    pos_emb_kernel<<<KLEN_, 256>>>();
    cudaMemcpyAsync(p_core, raw, CORE_BYTES, cudaMemcpyDeviceToDevice);
    if (out_mems)
        cudaMemcpyAsync(out_mems, raw, CORE_BYTES, cudaMemcpyDeviceToDevice);

    for (int l = 0; l < NLAYER; l++) {
        cudaMemcpyAsync(p_cat, mems + (size_t)l * CORE_N, CORE_BYTES, cudaMemcpyDeviceToDevice);
        cudaMemcpyAsync(p_cat + CORE_N, p_core, CORE_BYTES, cudaMemcpyDeviceToDevice);

        // w_heads = cat @ qkv_w[l]   (4096 x 3072 x 1024)
        gemm_tc<false,false><<<dim3(QKV3/128, (KLEN_*BSZ)/128), 256>>>(
            p_cat, qkvw + (size_t)l * DMODEL * QKV3, p_wheads, nullptr,
            KLEN_*BSZ, QKV3, DMODEL);

        // r_head_k = pos_emb @ r_w[l]   (2048 x 1024 x 1024)
        gemm_tc<false,false><<<dim3(DMODEL/128, KLEN_/128), 256>>>(
            p_pos, rw + (size_t)l * DMODEL * DMODEL, p_rhk, nullptr,
            KLEN_, DMODEL, DMODEL);

        // AC / BD batched GEMMs
        attn_qk_tc<0><<<dim3(KLEN_/128, QLEN/64, BSZ*NHEAD), 256>>>(rwb);
        attn_qk_tc<1><<<dim3(KLEN_/128, QLEN/64, BSZ*NHEAD), 256>>>(rrb);

        // fused rel-shift + mask + softmax
        softmax_kernel<<<dim3(QLEN, BSZ*NHEAD), 256>>>();

        // attn_vec = prob @ v
        attn_pv_tc<<<dim3(BSZ*NHEAD, QLEN/64), 256>>>();

        // attn_out = attn_vec @ o_w[l]
        gemm_tc<false,false><<<dim3(DMODEL/128, (QLEN*BSZ)/128), 256>>>(
            p_attnvec, ow + (size_t)l * DMODEL * DMODEL, p_tmp, nullptr,
            QLEN*BSZ, DMODEL, DMODEL);

        add_ln_kernel<<<QLEN*BSZ, 256>>>(p_tmp, ln1g + l*DMODEL, ln1b + l*DMODEL);

        gemm_tc<true,true><<<dim3(DMODEL/128, (QLEN*BSZ)/128), 256>>>(
            p_core, ffw1 + (size_t)l * DMODEL * DMODEL, p_ff1, ffb1 + l*DMODEL,
            QLEN*BSZ, DMODEL, DMODEL);

        gemm_tc<false,true><<<dim3(DMODEL/128, (QLEN*BSZ)/128), 256>>>(
            p_ff1, ffw2 + (size_t)l * DMODEL * DMODEL, p_tmp, ffb2 + l*DMODEL,
            QLEN*BSZ, DMODEL, DMODEL);

        add_ln_kernel<<<QLEN*BSZ, 256>>>(p_tmp, ln2g + l*DMODEL, ln2b + l*DMODEL);

        if (out_mems)
            cudaMemcpyAsync(out_mems + (size_t)(l+1) * CORE_N, p_core, CORE_BYTES,
                            cudaMemcpyDeviceToDevice);
    }

    if (out_core)
        cudaMemcpyAsync(out_core, p_core, CORE_BYTES, cudaMemcpyDeviceToDevice);
}